// round 11
// baseline (speedup 1.0000x reference)
#include <cuda_runtime.h>
#include <cuda_fp16.h>
#include <cstdint>

// ---------------- problem constants ----------------
namespace {
constexpr int kE = 512, kF = 2048, kQ = 8;
constexpr int kRows = 16384;

// GEMM tiling: 2 CTAs/SM
constexpr int BM = 128, BN = 128, BK = 64, STAGES = 3;
constexpr int GTHR = 256;                          // 8 warps: 2 (m) x 4 (n), warp tile 64x32
constexpr int STAGE_BYTES = BM * 128 + BN * 128;   // 32KB
constexpr int GSMEM = STAGES * STAGE_BYTES;        // 96KB
constexpr int NCHUNK = kF / BK;                    // 32

// act kernel (also converts w2 at its tail)
constexpr int ATHR = 256;
constexpr int AROWS = 64;
constexpr int ASM_W1 = 0;                          // f32 [8][2048] = 64KB
constexpr int ASM_B1 = 65536;                      // f32 [2048] = 8KB
constexpr int ASM_Z  = 73728;                      // f32 [64][8] = 2KB
constexpr int ASMEM  = 75776;
}

__device__ __align__(16) __half g_w2h[kE * kF];            // fp16 w2
__device__ __align__(16) __half g_act[(size_t)kRows * kF]; // fp16 relu(fc1), 64MB

// ---------------- helpers ----------------
__device__ __forceinline__ uint32_t smem_u32(const void* p) {
    uint32_t a;
    asm("{ .reg .u64 t; cvta.to.shared.u64 t, %1; cvt.u32.u64 %0, t; }" : "=r"(a) : "l"(p));
    return a;
}
__device__ __forceinline__ uint32_t sw128(uint32_t off) { return off ^ ((off >> 3) & 0x70); }

__device__ __forceinline__ void cp_async16(uint32_t dst, const void* src) {
    asm volatile("cp.async.cg.shared.global [%0], [%1], 16;" :: "r"(dst), "l"(src) : "memory");
}
__device__ __forceinline__ void cp_commit() {
    asm volatile("cp.async.commit_group;" ::: "memory");
}
__device__ __forceinline__ void cp_wait1() {
    asm volatile("cp.async.wait_group 1;" ::: "memory");
}

__device__ __forceinline__ void ldsm4(uint32_t* r, uint32_t addr) {
    asm volatile("ldmatrix.sync.aligned.m8n8.x4.shared.b16 {%0,%1,%2,%3}, [%4];"
        : "=r"(r[0]), "=r"(r[1]), "=r"(r[2]), "=r"(r[3]) : "r"(addr));
}
__device__ __forceinline__ void mma16816(float* d, const uint32_t* a, const uint32_t* b) {
    asm volatile(
        "mma.sync.aligned.m16n8k16.row.col.f32.f16.f16.f32 "
        "{%0,%1,%2,%3}, {%4,%5,%6,%7}, {%8,%9}, {%0,%1,%2,%3};"
        : "+f"(d[0]), "+f"(d[1]), "+f"(d[2]), "+f"(d[3])
        : "r"(a[0]), "r"(a[1]), "r"(a[2]), "r"(a[3]), "r"(b[0]), "r"(b[1]));
}

// ---------------- kernel 1: fused act (+ w2 convert tail) ----------------
__global__ void __launch_bounds__(ATHR, 2)
ffq_act(const float* __restrict__ x, const float* __restrict__ ry,
        const float* __restrict__ w1, const float* __restrict__ b1,
        const float* __restrict__ w2) {
    extern __shared__ char smem[];
    float* w1t = reinterpret_cast<float*>(smem + ASM_W1);  // [q][f]
    float* b1s = reinterpret_cast<float*>(smem + ASM_B1);
    float* zs  = reinterpret_cast<float*>(smem + ASM_Z);   // [row][q]
    const int tid = threadIdx.x;

    // ---- w2 convert share: 256 blocks x 256 thr x 4 float4 = 12MB ----
    {
        const int base = (blockIdx.x * ATHR + tid) * 4;    // float4 index
        __half2* dst = reinterpret_cast<__half2*>(g_w2h);
#pragma unroll
        for (int j = 0; j < 4; j++) {
            float4 v = __ldg(reinterpret_cast<const float4*>(w2) + base + j);
            dst[2 * (base + j)]     = __floats2half2_rn(v.x, v.y);
            dst[2 * (base + j) + 1] = __floats2half2_rn(v.z, v.w);
        }
    }

    {   // stage w1 transposed: thread covers f = tid*8 .. +7
        const int f = tid * 8;
#pragma unroll
        for (int j = 0; j < 8; j++) {
            const float4* p = reinterpret_cast<const float4*>(w1 + (size_t)(f + j) * kQ);
            float4 a = __ldg(p), b = __ldg(p + 1);
            w1t[0 * kF + f + j] = a.x; w1t[1 * kF + f + j] = a.y;
            w1t[2 * kF + f + j] = a.z; w1t[3 * kF + f + j] = a.w;
            w1t[4 * kF + f + j] = b.x; w1t[5 * kF + f + j] = b.y;
            w1t[6 * kF + f + j] = b.z; w1t[7 * kF + f + j] = b.w;
        }
        *reinterpret_cast<float4*>(b1s + f)     = __ldg(reinterpret_cast<const float4*>(b1 + f));
        *reinterpret_cast<float4*>(b1s + f + 4) = __ldg(reinterpret_cast<const float4*>(b1 + f + 4));
    }
    if (tid < AROWS) {
        const float4* xp =
            reinterpret_cast<const float4*>(x + (size_t)(blockIdx.x * AROWS + tid) * kE);
        float4 a = __ldg(xp), b = __ldg(xp + 1);
        float xs[8] = {a.x, a.y, a.z, a.w, b.x, b.y, b.z, b.w};
#pragma unroll
        for (int q = 0; q < 8; q++) zs[tid * 8 + q] = cosf(xs[q]) * cosf(__ldg(ry + q));
    }
    __syncthreads();

    const int w = tid >> 5, lane = tid & 31;
#pragma unroll 1
    for (int fi = 0; fi < 8; fi++) {
        const int f0 = fi * 256 + lane * 8;
        float4 wq[8][2];
#pragma unroll
        for (int q = 0; q < 8; q++) {
            wq[q][0] = *reinterpret_cast<const float4*>(w1t + q * kF + f0);
            wq[q][1] = *reinterpret_cast<const float4*>(w1t + q * kF + f0 + 4);
        }
        const float4 bq0 = *reinterpret_cast<const float4*>(b1s + f0);
        const float4 bq1 = *reinterpret_cast<const float4*>(b1s + f0 + 4);
#pragma unroll
        for (int rr = 0; rr < 8; rr++) {
            const int rl = w * 8 + rr;
            const float4 z0 = *reinterpret_cast<const float4*>(zs + rl * 8);
            const float4 z1 = *reinterpret_cast<const float4*>(zs + rl * 8 + 4);
            const float zq[8] = {z0.x, z0.y, z0.z, z0.w, z1.x, z1.y, z1.z, z1.w};
            float h[8] = {bq0.x, bq0.y, bq0.z, bq0.w, bq1.x, bq1.y, bq1.z, bq1.w};
#pragma unroll
            for (int q = 0; q < 8; q++) {
                const float z = zq[q];
                h[0] = fmaf(z, wq[q][0].x, h[0]); h[1] = fmaf(z, wq[q][0].y, h[1]);
                h[2] = fmaf(z, wq[q][0].z, h[2]); h[3] = fmaf(z, wq[q][0].w, h[3]);
                h[4] = fmaf(z, wq[q][1].x, h[4]); h[5] = fmaf(z, wq[q][1].y, h[5]);
                h[6] = fmaf(z, wq[q][1].z, h[6]); h[7] = fmaf(z, wq[q][1].w, h[7]);
            }
            __half2 p0 = __floats2half2_rn(fmaxf(h[0], 0.f), fmaxf(h[1], 0.f));
            __half2 p1 = __floats2half2_rn(fmaxf(h[2], 0.f), fmaxf(h[3], 0.f));
            __half2 p2 = __floats2half2_rn(fmaxf(h[4], 0.f), fmaxf(h[5], 0.f));
            __half2 p3 = __floats2half2_rn(fmaxf(h[6], 0.f), fmaxf(h[7], 0.f));
            uint4 pk;
            pk.x = *reinterpret_cast<uint32_t*>(&p0);
            pk.y = *reinterpret_cast<uint32_t*>(&p1);
            pk.z = *reinterpret_cast<uint32_t*>(&p2);
            pk.w = *reinterpret_cast<uint32_t*>(&p3);
            const size_t row = (size_t)blockIdx.x * AROWS + rl;
            *reinterpret_cast<uint4*>(g_act + row * kF + f0) = pk;
        }
    }
}

// ---------------- kernel 2: GEMM out = act @ w2^T + b2, 2 CTAs/SM ----------------
__global__ void __launch_bounds__(GTHR, 2)
ffq_gemm(const float* __restrict__ b2, float* __restrict__ out) {
    extern __shared__ char smem[];
    const uint32_t sb = smem_u32(smem);
    const int tid  = threadIdx.x;
    const int lane = tid & 31;
    const int wid  = tid >> 5;
    const int wm   = wid >> 2;            // 0..1 (m)
    const int wn   = wid & 3;             // 0..3 (n)
    const int m0   = (blockIdx.x >> 2) * BM;
    const int n0   = (blockIdx.x & 3) * BN;

    // per-thread fill addressing (8 x 16B segs each for A and B)
    const int fr = tid >> 3, fj = tid & 7;
    const uint32_t aoff = sw128((uint32_t)(fr * 128 + fj * 16));
    const __half* asrc0 = g_act + (size_t)(m0 + fr) * kF + fj * 8;
    const __half* bsrc0 = g_w2h + (size_t)(n0 + fr) * kF + fj * 8;

    // full-chunk fill (prologue only)
    auto fill_all = [&](int st, int c) {
        const uint32_t As = sb + st * STAGE_BYTES;
        const uint32_t Bs = As + BM * 128;
#pragma unroll
        for (int i = 0; i < 4; i++) {
            cp_async16(As + aoff + (uint32_t)(i * 4096), asrc0 + (size_t)(i * 32) * kF + c * BK);
            cp_async16(Bs + aoff + (uint32_t)(i * 4096), bsrc0 + (size_t)(i * 32) * kF + c * BK);
        }
    };
    // partial fill: quarter q of chunk c (spread across kc iters)
    auto fill_part = [&](int st, int c, int q) {
        const uint32_t As = sb + st * STAGE_BYTES;
        const uint32_t Bs = As + BM * 128;
        cp_async16(As + aoff + (uint32_t)(q * 4096), asrc0 + (size_t)(q * 32) * kF + c * BK);
        cp_async16(Bs + aoff + (uint32_t)(q * 4096), bsrc0 + (size_t)(q * 32) * kF + c * BK);
    };

    fill_all(0, 0); cp_commit();
    fill_all(1, 1); cp_commit();

    float acc[4][4][4];
#pragma unroll
    for (int mi = 0; mi < 4; mi++)
#pragma unroll
        for (int ni = 0; ni < 4; ni++)
#pragma unroll
            for (int j = 0; j < 4; j++) acc[mi][ni][j] = 0.f;

    const uint32_t xm     = (uint32_t)((lane & 7) << 4);
    const uint32_t a_rowb = (uint32_t)(wm * 64 + (lane & 15)) * 128;
    const uint32_t b_rowb = (uint32_t)(wn * 32 + ((lane >> 4) & 1) * 8 + (lane & 7)) * 128;
    const uint32_t a_c0 = (uint32_t)((lane >> 4) * 16);
    const uint32_t b_c0 = (uint32_t)(((lane >> 3) & 1) * 16);

#pragma unroll 1
    for (int c = 0; c < NCHUNK; c++) {
        cp_wait1();
        __syncthreads();

        const uint32_t Ab = sb + (c % STAGES) * STAGE_BYTES;
        const uint32_t Bb = Ab + BM * 128;
        const int pf_st = (c + 2) % STAGES;
        const bool pf = (c + 2 < NCHUNK);

        uint32_t af[2][4][4], bf[2][2][4];
        // kc0 frags FIRST (tensor pipe starts asap)
#pragma unroll
        for (int mi = 0; mi < 4; mi++)
            ldsm4(af[0][mi], Ab + a_rowb + (uint32_t)(mi * 2048) + (a_c0 ^ xm));
#pragma unroll
        for (int np = 0; np < 2; np++)
            ldsm4(bf[0][np], Bb + b_rowb + (uint32_t)(np * 2048) + (b_c0 ^ xm));

#pragma unroll
        for (int kc = 0; kc < 4; kc++) {
            const int cur = kc & 1, nxt = cur ^ 1;
            if (pf) fill_part(pf_st, c + 2, kc);   // spread LDGSTS across kc iters
            if (kc < 3) {
                const uint32_t ac = ((a_c0 + (uint32_t)((kc + 1) * 32)) ^ xm);
                const uint32_t bc = ((b_c0 + (uint32_t)((kc + 1) * 32)) ^ xm);
#pragma unroll
                for (int mi = 0; mi < 4; mi++)
                    ldsm4(af[nxt][mi], Ab + a_rowb + (uint32_t)(mi * 2048) + ac);
#pragma unroll
                for (int np = 0; np < 2; np++)
                    ldsm4(bf[nxt][np], Bb + b_rowb + (uint32_t)(np * 2048) + bc);
            }
#pragma unroll
            for (int mi = 0; mi < 4; mi++)
#pragma unroll
                for (int ni = 0; ni < 4; ni++) {
                    uint32_t bb[2] = {bf[cur][ni >> 1][(ni & 1) * 2],
                                      bf[cur][ni >> 1][(ni & 1) * 2 + 1]};
                    mma16816(acc[mi][ni], af[cur][mi], bb);
                }
        }
        cp_commit();
    }

    // epilogue
#pragma unroll
    for (int ni = 0; ni < 4; ni++) {
        const int colp = n0 + wn * 32 + ni * 8 + (lane & 3) * 2;
        const float2 bv = __ldg(reinterpret_cast<const float2*>(b2 + colp));
#pragma unroll
        for (int mi = 0; mi < 4; mi++) {
            const int row0 = m0 + wm * 64 + mi * 16 + (lane >> 2);
            float2 v0 = make_float2(acc[mi][ni][0] + bv.x, acc[mi][ni][1] + bv.y);
            float2 v1 = make_float2(acc[mi][ni][2] + bv.x, acc[mi][ni][3] + bv.y);
            *reinterpret_cast<float2*>(out + (size_t)row0 * kE + colp) = v0;
            *reinterpret_cast<float2*>(out + (size_t)(row0 + 8) * kE + colp) = v1;
        }
    }
}

// ---------------- launch ----------------
extern "C" void kernel_launch(void* const* d_in, const int* in_sizes, int n_in,
                              void* d_out, int out_size) {
    (void)in_sizes; (void)n_in; (void)out_size;
    const float* x  = (const float*)d_in[0];
    const float* ry = (const float*)d_in[1];
    const float* w1 = (const float*)d_in[2];
    const float* b1 = (const float*)d_in[3];
    const float* w2 = (const float*)d_in[4];
    const float* b2 = (const float*)d_in[5];
    float* out = (float*)d_out;

    cudaFuncSetAttribute(ffq_act, cudaFuncAttributeMaxDynamicSharedMemorySize, ASMEM);
    ffq_act<<<kRows / AROWS, ATHR, ASMEM>>>(x, ry, w1, b1, w2);

    cudaFuncSetAttribute(ffq_gemm, cudaFuncAttributeMaxDynamicSharedMemorySize, GSMEM);
    ffq_gemm<<<(kRows / BM) * (kE / BN), GTHR, GSMEM>>>(b2, out);
}

// round 16
// speedup vs baseline: 1.6145x; 1.6145x over previous
#include <cuda_runtime.h>
#include <cuda_fp16.h>
#include <cstdint>

// ---------------- problem constants ----------------
namespace {
constexpr int kE = 512, kF = 2048, kQ = 8;
constexpr int kRows = 16384;

// GEMM tiling: 2 CTAs/SM
constexpr int BM = 128, BN = 128, BK = 64, STAGES = 3;
constexpr int GTHR = 256;                          // 8 warps: 2 (m) x 4 (n), warp tile 64x32
constexpr int STAGE_BYTES = BM * 128 + BN * 128;   // 32KB
constexpr int GSMEM = STAGES * STAGE_BYTES;        // 96KB
constexpr int NCHUNK = kF / BK;                    // 32

// act kernel
constexpr int ATHR = 256;
constexpr int AROWS = 64;
constexpr int ASM_W1 = 0;                          // f32 [8][2048] = 64KB
constexpr int ASM_B1 = 65536;                      // f32 [2048] = 8KB
constexpr int ASM_Z  = 73728;                      // f32 [64][8] = 2KB
constexpr int ASMEM  = 75776;
}

__device__ __align__(16) __half g_w2h[kE * kF];            // fp16 w2
__device__ __align__(16) __half g_act[(size_t)kRows * kF]; // fp16 relu(fc1), 64MB

// ---------------- helpers ----------------
__device__ __forceinline__ uint32_t smem_u32(const void* p) {
    uint32_t a;
    asm("{ .reg .u64 t; cvta.to.shared.u64 t, %1; cvt.u32.u64 %0, t; }" : "=r"(a) : "l"(p));
    return a;
}
__device__ __forceinline__ uint32_t sw128(uint32_t off) { return off ^ ((off >> 3) & 0x70); }

__device__ __forceinline__ void cp_async16(uint32_t dst, const void* src) {
    asm volatile("cp.async.cg.shared.global [%0], [%1], 16;" :: "r"(dst), "l"(src) : "memory");
}
__device__ __forceinline__ void cp_commit() {
    asm volatile("cp.async.commit_group;" ::: "memory");
}
__device__ __forceinline__ void cp_wait1() {
    asm volatile("cp.async.wait_group 1;" ::: "memory");
}

__device__ __forceinline__ void ldsm4(uint32_t* r, uint32_t addr) {
    asm volatile("ldmatrix.sync.aligned.m8n8.x4.shared.b16 {%0,%1,%2,%3}, [%4];"
        : "=r"(r[0]), "=r"(r[1]), "=r"(r[2]), "=r"(r[3]) : "r"(addr));
}
__device__ __forceinline__ void mma16816(float* d, const uint32_t* a, const uint32_t* b) {
    asm volatile(
        "mma.sync.aligned.m16n8k16.row.col.f32.f16.f16.f32 "
        "{%0,%1,%2,%3}, {%4,%5,%6,%7}, {%8,%9}, {%0,%1,%2,%3};"
        : "+f"(d[0]), "+f"(d[1]), "+f"(d[2]), "+f"(d[3])
        : "r"(a[0]), "r"(a[1]), "r"(a[2]), "r"(a[3]), "r"(b[0]), "r"(b[1]));
}

// ---------------- kernel 1: w2 -> fp16 ----------------
__global__ void ffq_convert_w2(const float* __restrict__ w2) {
    int i = blockIdx.x * blockDim.x + threadIdx.x;
    float4 v = __ldg(reinterpret_cast<const float4*>(w2) + i);
    __half2* dst = reinterpret_cast<__half2*>(g_w2h);
    dst[2 * i]     = __floats2half2_rn(v.x, v.y);
    dst[2 * i + 1] = __floats2half2_rn(v.z, v.w);
}

// ---------------- kernel 2: fused quantum + fc1 + relu -> fp16 act ----------------
__global__ void __launch_bounds__(ATHR, 2)
ffq_act(const float* __restrict__ x, const float* __restrict__ ry,
        const float* __restrict__ w1, const float* __restrict__ b1) {
    extern __shared__ char smem[];
    float* w1t = reinterpret_cast<float*>(smem + ASM_W1);  // [q][f]
    float* b1s = reinterpret_cast<float*>(smem + ASM_B1);
    float* zs  = reinterpret_cast<float*>(smem + ASM_Z);   // [row][q]
    const int tid = threadIdx.x;

    {   // stage w1 transposed: thread covers f = tid*8 .. +7
        const int f = tid * 8;
#pragma unroll
        for (int j = 0; j < 8; j++) {
            const float4* p = reinterpret_cast<const float4*>(w1 + (size_t)(f + j) * kQ);
            float4 a = __ldg(p), b = __ldg(p + 1);
            w1t[0 * kF + f + j] = a.x; w1t[1 * kF + f + j] = a.y;
            w1t[2 * kF + f + j] = a.z; w1t[3 * kF + f + j] = a.w;
            w1t[4 * kF + f + j] = b.x; w1t[5 * kF + f + j] = b.y;
            w1t[6 * kF + f + j] = b.z; w1t[7 * kF + f + j] = b.w;
        }
        *reinterpret_cast<float4*>(b1s + f)     = __ldg(reinterpret_cast<const float4*>(b1 + f));
        *reinterpret_cast<float4*>(b1s + f + 4) = __ldg(reinterpret_cast<const float4*>(b1 + f + 4));
    }
    if (tid < AROWS) {
        const float4* xp =
            reinterpret_cast<const float4*>(x + (size_t)(blockIdx.x * AROWS + tid) * kE);
        float4 a = __ldg(xp), b = __ldg(xp + 1);
        float xs[8] = {a.x, a.y, a.z, a.w, b.x, b.y, b.z, b.w};
#pragma unroll
        for (int q = 0; q < 8; q++) zs[tid * 8 + q] = cosf(xs[q]) * cosf(__ldg(ry + q));
    }
    __syncthreads();

    const int w = tid >> 5, lane = tid & 31;
#pragma unroll 1
    for (int fi = 0; fi < 8; fi++) {
        const int f0 = fi * 256 + lane * 8;
        float4 wq[8][2];
#pragma unroll
        for (int q = 0; q < 8; q++) {
            wq[q][0] = *reinterpret_cast<const float4*>(w1t + q * kF + f0);
            wq[q][1] = *reinterpret_cast<const float4*>(w1t + q * kF + f0 + 4);
        }
        const float4 bq0 = *reinterpret_cast<const float4*>(b1s + f0);
        const float4 bq1 = *reinterpret_cast<const float4*>(b1s + f0 + 4);
#pragma unroll
        for (int rr = 0; rr < 8; rr++) {
            const int rl = w * 8 + rr;
            const float4 z0 = *reinterpret_cast<const float4*>(zs + rl * 8);
            const float4 z1 = *reinterpret_cast<const float4*>(zs + rl * 8 + 4);
            const float zq[8] = {z0.x, z0.y, z0.z, z0.w, z1.x, z1.y, z1.z, z1.w};
            float h[8] = {bq0.x, bq0.y, bq0.z, bq0.w, bq1.x, bq1.y, bq1.z, bq1.w};
#pragma unroll
            for (int q = 0; q < 8; q++) {
                const float z = zq[q];
                h[0] = fmaf(z, wq[q][0].x, h[0]); h[1] = fmaf(z, wq[q][0].y, h[1]);
                h[2] = fmaf(z, wq[q][0].z, h[2]); h[3] = fmaf(z, wq[q][0].w, h[3]);
                h[4] = fmaf(z, wq[q][1].x, h[4]); h[5] = fmaf(z, wq[q][1].y, h[5]);
                h[6] = fmaf(z, wq[q][1].z, h[6]); h[7] = fmaf(z, wq[q][1].w, h[7]);
            }
            __half2 p0 = __floats2half2_rn(fmaxf(h[0], 0.f), fmaxf(h[1], 0.f));
            __half2 p1 = __floats2half2_rn(fmaxf(h[2], 0.f), fmaxf(h[3], 0.f));
            __half2 p2 = __floats2half2_rn(fmaxf(h[4], 0.f), fmaxf(h[5], 0.f));
            __half2 p3 = __floats2half2_rn(fmaxf(h[6], 0.f), fmaxf(h[7], 0.f));
            uint4 pk;
            pk.x = *reinterpret_cast<uint32_t*>(&p0);
            pk.y = *reinterpret_cast<uint32_t*>(&p1);
            pk.z = *reinterpret_cast<uint32_t*>(&p2);
            pk.w = *reinterpret_cast<uint32_t*>(&p3);
            const size_t row = (size_t)blockIdx.x * AROWS + rl;
            *reinterpret_cast<uint4*>(g_act + row * kF + f0) = pk;
        }
    }
}

// ---------------- kernel 3: GEMM out = act @ w2^T + b2, 2 CTAs/SM ----------------
__global__ void __launch_bounds__(GTHR, 2)
ffq_gemm(const float* __restrict__ b2, float* __restrict__ out) {
    extern __shared__ char smem[];
    const uint32_t sb = smem_u32(smem);
    const int tid  = threadIdx.x;
    const int lane = tid & 31;
    const int wid  = tid >> 5;
    const int wm   = wid >> 2;            // 0..1 (m)
    const int wn   = wid & 3;             // 0..3 (n)
    const int m0   = (blockIdx.x >> 2) * BM;
    const int n0   = (blockIdx.x & 3) * BN;

    // per-thread fill addressing (8 x 16B segs each for A and B)
    const int fr = tid >> 3, fj = tid & 7;
    const uint32_t aoff = sw128((uint32_t)(fr * 128 + fj * 16));
    const __half* asrc0 = g_act + (size_t)(m0 + fr) * kF + fj * 8;
    const __half* bsrc0 = g_w2h + (size_t)(n0 + fr) * kF + fj * 8;

    auto fill_all = [&](int st, int c) {
        const uint32_t As = sb + st * STAGE_BYTES;
        const uint32_t Bs = As + BM * 128;
#pragma unroll
        for (int i = 0; i < 4; i++) {
            cp_async16(As + aoff + (uint32_t)(i * 4096), asrc0 + (size_t)(i * 32) * kF + c * BK);
            cp_async16(Bs + aoff + (uint32_t)(i * 4096), bsrc0 + (size_t)(i * 32) * kF + c * BK);
        }
    };

    fill_all(0, 0); cp_commit();
    fill_all(1, 1); cp_commit();

    float acc[4][4][4];
#pragma unroll
    for (int mi = 0; mi < 4; mi++)
#pragma unroll
        for (int ni = 0; ni < 4; ni++)
#pragma unroll
            for (int j = 0; j < 4; j++) acc[mi][ni][j] = 0.f;

    const uint32_t xm     = (uint32_t)((lane & 7) << 4);
    const uint32_t a_rowb = (uint32_t)(wm * 64 + (lane & 15)) * 128;
    const uint32_t b_rowb = (uint32_t)(wn * 32 + ((lane >> 4) & 1) * 8 + (lane & 7)) * 128;
    const uint32_t a_c0 = (uint32_t)((lane >> 4) * 16);
    const uint32_t b_c0 = (uint32_t)(((lane >> 3) & 1) * 16);

    // one chunk iteration; st/pst are compile-time per call site
    auto chunk_iter = [&](int c, int st, int pst) __attribute__((always_inline)) {
        cp_wait1();
        __syncthreads();
        if (c + 2 < NCHUNK) fill_all(pst, c + 2);
        cp_commit();

        const uint32_t Ab = sb + st * STAGE_BYTES;
        const uint32_t Bb = Ab + BM * 128;

        uint32_t af[2][4][4], bf[2][2][4];
#pragma unroll
        for (int mi = 0; mi < 4; mi++)
            ldsm4(af[0][mi], Ab + a_rowb + (uint32_t)(mi * 2048) + (a_c0 ^ xm));
#pragma unroll
        for (int np = 0; np < 2; np++)
            ldsm4(bf[0][np], Bb + b_rowb + (uint32_t)(np * 2048) + (b_c0 ^ xm));

#pragma unroll
        for (int kc = 0; kc < 4; kc++) {
            const int cur = kc & 1, nxt = cur ^ 1;
            if (kc < 3) {   // prefetch kc+1 frags; independent of mma below
                const uint32_t ac = ((a_c0 + (uint32_t)((kc + 1) * 32)) ^ xm);
                const uint32_t bc = ((b_c0 + (uint32_t)((kc + 1) * 32)) ^ xm);
#pragma unroll
                for (int mi = 0; mi < 4; mi++)
                    ldsm4(af[nxt][mi], Ab + a_rowb + (uint32_t)(mi * 2048) + ac);
#pragma unroll
                for (int np = 0; np < 2; np++)
                    ldsm4(bf[nxt][np], Bb + b_rowb + (uint32_t)(np * 2048) + bc);
            }
#pragma unroll
            for (int mi = 0; mi < 4; mi++)
#pragma unroll
                for (int ni = 0; ni < 4; ni++) {
                    uint32_t bb[2] = {bf[cur][ni >> 1][(ni & 1) * 2],
                                      bf[cur][ni >> 1][(ni & 1) * 2 + 1]};
                    mma16816(acc[mi][ni], af[cur][mi], bb);
                }
        }
    };

    // stage-residue unrolled chunk loop: st = c%3 as literals
#pragma unroll 1
    for (int cb = 0; cb < NCHUNK; cb += 3) {
        chunk_iter(cb, 0, 2);
        if (cb + 1 < NCHUNK) chunk_iter(cb + 1, 1, 0);
        if (cb + 2 < NCHUNK) chunk_iter(cb + 2, 2, 1);
    }

    // epilogue
#pragma unroll
    for (int ni = 0; ni < 4; ni++) {
        const int colp = n0 + wn * 32 + ni * 8 + (lane & 3) * 2;
        const float2 bv = __ldg(reinterpret_cast<const float2*>(b2 + colp));
#pragma unroll
        for (int mi = 0; mi < 4; mi++) {
            const int row0 = m0 + wm * 64 + mi * 16 + (lane >> 2);
            float2 v0 = make_float2(acc[mi][ni][0] + bv.x, acc[mi][ni][1] + bv.y);
            float2 v1 = make_float2(acc[mi][ni][2] + bv.x, acc[mi][ni][3] + bv.y);
            *reinterpret_cast<float2*>(out + (size_t)row0 * kE + colp) = v0;
            *reinterpret_cast<float2*>(out + (size_t)(row0 + 8) * kE + colp) = v1;
        }
    }
}

// ---------------- launch ----------------
extern "C" void kernel_launch(void* const* d_in, const int* in_sizes, int n_in,
                              void* d_out, int out_size) {
    (void)in_sizes; (void)n_in; (void)out_size;
    const float* x  = (const float*)d_in[0];
    const float* ry = (const float*)d_in[1];
    const float* w1 = (const float*)d_in[2];
    const float* b1 = (const float*)d_in[3];
    const float* w2 = (const float*)d_in[4];
    const float* b2 = (const float*)d_in[5];
    float* out = (float*)d_out;

    ffq_convert_w2<<<1024, 256>>>(w2);

    cudaFuncSetAttribute(ffq_act, cudaFuncAttributeMaxDynamicSharedMemorySize, ASMEM);
    ffq_act<<<kRows / AROWS, ATHR, ASMEM>>>(x, ry, w1, b1);

    cudaFuncSetAttribute(ffq_gemm, cudaFuncAttributeMaxDynamicSharedMemorySize, GSMEM);
    ffq_gemm<<<(kRows / BM) * (kE / BN), GTHR, GSMEM>>>(b2, out);
}